// round 4
// baseline (speedup 1.0000x reference)
#include <cuda_runtime.h>
#include <cuda_fp16.h>
#include <cstdint>

// ---------------------------------------------------------------------------
// int4 group-quantized GEMM via mma.sync (HMMA). Harness I/O is float32
// (fp16 jax arrays are materialized as fp32): x fp32, weight_packed int32,
// scales fp32, y fp32. A pre-kernel converts x/scales to fp16 scratch;
// the main GEMM is the fp16 HMMA pipeline.
// y[512, 11008] = x[512, 4096] @ dequant(W)[11008, 4096]^T
// W: one byte per int32 (low nibble = even k, high nibble = odd k)
// w = scale[n, k/128] * (q - 8)
// ---------------------------------------------------------------------------

#define M_TOTAL 512
#define N_TOTAL 11008
#define K_TOTAL 4096
#define KW_INT  2048
#define NGROUPS 32

#define MT 128
#define NT 128
#define KT 64
#define NSTAGES (K_TOTAL / KT)  // 64
#define THREADS 256

#define SWZ128(bo) ((bo) ^ (((bo) >> 3) & 0x70))

#define STAGE_BYTES (128 * 128)
#define SMEM_A_OFF(buf) ((buf) * STAGE_BYTES)
#define SMEM_B_OFF(buf) (2 * STAGE_BYTES + (buf) * STAGE_BYTES)
#define SMEM_TOTAL (4 * STAGE_BYTES)

// fp16 scratch (device globals: allocation-free scratch)
__device__ __half g_xh[M_TOTAL * K_TOTAL];        // 4 MB
__device__ __half g_sh[N_TOTAL * NGROUPS];        // 0.69 MB

// ---------------- PTX helpers ----------------
__device__ __forceinline__ uint32_t smem_u32(const void* p) {
    uint32_t a;
    asm("{ .reg .u64 t; cvta.to.shared.u64 t, %1; cvt.u32.u64 %0, t; }"
        : "=r"(a) : "l"(p));
    return a;
}

__device__ __forceinline__ void cp_async16(uint32_t saddr, const void* g) {
    asm volatile("cp.async.cg.shared.global [%0], [%1], 16;"
                 :: "r"(saddr), "l"(g) : "memory");
}
#define CP_COMMIT() asm volatile("cp.async.commit_group;" ::: "memory")
#define CP_WAIT0()  asm volatile("cp.async.wait_group 0;" ::: "memory")

__device__ __forceinline__ void ldsm4(uint32_t* r, uint32_t a) {
    asm volatile("ldmatrix.sync.aligned.m8n8.x4.shared.b16 {%0,%1,%2,%3}, [%4];"
                 : "=r"(r[0]), "=r"(r[1]), "=r"(r[2]), "=r"(r[3]) : "r"(a));
}

__device__ __forceinline__ void mma16816(float* c, const uint32_t* a,
                                         const uint32_t* b) {
    asm volatile(
        "mma.sync.aligned.m16n8k16.row.col.f32.f16.f16.f32 "
        "{%0,%1,%2,%3}, {%4,%5,%6,%7}, {%8,%9}, {%0,%1,%2,%3};"
        : "+f"(c[0]), "+f"(c[1]), "+f"(c[2]), "+f"(c[3])
        : "r"(a[0]), "r"(a[1]), "r"(a[2]), "r"(a[3]), "r"(b[0]), "r"(b[1]));
}

// dequant one packed byte -> half2 {lo-8, hi-8} * s2
// exact: (q | 0x6400) as fp16 == 1024 + q; subtract 1032.
__device__ __forceinline__ __half2 dq(int b, __half2 s2, __half2 c1032) {
    uint32_t u = (uint32_t)(b & 0xF) | (((uint32_t)b << 12) & 0x000F0000u)
               | 0x64006400u;
    __half2 h = __hsub2(*reinterpret_cast<__half2*>(&u), c1032);
    return __hmul2(h, s2);
}

// ---------------- fp32 -> fp16 conversion kernel ----------------
#define XV (M_TOTAL * K_TOTAL / 4)      // 524288 float4s
#define SV (N_TOTAL * NGROUPS / 4)      // 88064 float4s

__global__ void __launch_bounds__(256)
cvt_kernel(const float* __restrict__ x, const float* __restrict__ sc) {
    int i = blockIdx.x * blockDim.x + threadIdx.x;
    if (i < XV) {
        float4 f = reinterpret_cast<const float4*>(x)[i];
        union { __half2 h[2]; uint2 u; } p;
        p.h[0] = __floats2half2_rn(f.x, f.y);
        p.h[1] = __floats2half2_rn(f.z, f.w);
        reinterpret_cast<uint2*>(g_xh)[i] = p.u;
    } else if (i < XV + SV) {
        int j = i - XV;
        float4 f = reinterpret_cast<const float4*>(sc)[j];
        union { __half2 h[2]; uint2 u; } p;
        p.h[0] = __floats2half2_rn(f.x, f.y);
        p.h[1] = __floats2half2_rn(f.z, f.w);
        reinterpret_cast<uint2*>(g_sh)[j] = p.u;
    }
}

// ---------------- main GEMM kernel ----------------
__global__ void __launch_bounds__(THREADS, 2)
int4_gemm_hmma(const int* __restrict__ wp, float* __restrict__ y) {
    extern __shared__ __align__(1024) char smem[];
    const uint32_t sbase = smem_u32(smem);

    const int tid = threadIdx.x;
    const int wid = tid >> 5;
    const int lid = tid & 31;
    const int wm = (wid >> 2) * 64;
    const int wn = (wid & 3) * 32;

    const int m0 = blockIdx.x * MT;   // fast dim: 4 M tiles share weights in L2
    const int n0 = blockIdx.y * NT;

    const int jA = lid >> 3, rA = lid & 7;
    const int a_row_l = (jA & 1) * 8 + rA;
    const int a_kb_l  = (jA >> 1) * 16;
    const int b_row_l = (jA >> 1) * 8 + rA;
    const int b_kb_l  = (jA & 1) * 16;

    const int brow = tid >> 1;
    const int bseg = tid & 1;
    const __half2 c1032 = __half2half2(__ushort_as_half((unsigned short)0x6408));

    float acc[4][4][4];
    #pragma unroll
    for (int i = 0; i < 4; ++i)
        #pragma unroll
        for (int j = 0; j < 4; ++j)
            #pragma unroll
            for (int k = 0; k < 4; ++k) acc[i][j][k] = 0.f;

    auto issue_a = [&](int k0, int buf) {
        const uint32_t abase = sbase + SMEM_A_OFF(buf);
        #pragma unroll
        for (int it = 0; it < 4; ++it) {
            int t = tid + it * THREADS;
            int row = t >> 3, ch = t & 7;
            const void* src = g_xh + (size_t)(m0 + row) * K_TOTAL + k0 + ch * 8;
            uint32_t bo = row * 128 + ch * 16;
            cp_async16(abase + SWZ128(bo), src);
        }
    };

    int4 bp[4];
    __half2 s2;
    auto load_b = [&](int k0) {
        const int4* gb = reinterpret_cast<const int4*>(
            wp + (size_t)(n0 + brow) * KW_INT + (k0 >> 1) + bseg * 16);
        #pragma unroll
        for (int j = 0; j < 4; ++j) bp[j] = gb[j];
        const __half s = g_sh[(size_t)(n0 + brow) * NGROUPS + (k0 >> 7)];
        s2 = __half2half2(s);
    };

    auto store_b = [&](int buf) {
        #pragma unroll
        for (int j = 0; j < 4; ++j) {
            union { __half2 h[4]; uint4 u; } pk;
            pk.h[0] = dq(bp[j].x, s2, c1032);
            pk.h[1] = dq(bp[j].y, s2, c1032);
            pk.h[2] = dq(bp[j].z, s2, c1032);
            pk.h[3] = dq(bp[j].w, s2, c1032);
            uint32_t bo = brow * 128 + bseg * 64 + j * 16;
            *reinterpret_cast<uint4*>(smem + SMEM_B_OFF(buf) + SWZ128(bo)) = pk.u;
        }
    };

    // prologue
    issue_a(0, 0);
    CP_COMMIT();
    load_b(0);
    store_b(0);
    CP_WAIT0();
    __syncthreads();

    for (int st = 0; st < NSTAGES; ++st) {
        const int buf = st & 1;

        if (st + 1 < NSTAGES) {
            const int k1 = (st + 1) * KT;
            issue_a(k1, buf ^ 1);
            CP_COMMIT();
            load_b(k1);
        }

        const uint32_t abase = sbase + SMEM_A_OFF(buf);
        const uint32_t bbase = sbase + SMEM_B_OFF(buf);
        #pragma unroll
        for (int ks = 0; ks < 4; ++ks) {
            const int kb = ks * 32;
            uint32_t af[4][4];
            #pragma unroll
            for (int mt = 0; mt < 4; ++mt) {
                uint32_t bo = (uint32_t)(wm + mt * 16 + a_row_l) * 128
                            + kb + a_kb_l;
                ldsm4(af[mt], abase + SWZ128(bo));
            }
            uint32_t bf[2][4];
            #pragma unroll
            for (int np = 0; np < 2; ++np) {
                uint32_t bo = (uint32_t)(wn + np * 16 + b_row_l) * 128
                            + kb + b_kb_l;
                ldsm4(bf[np], bbase + SWZ128(bo));
            }
            #pragma unroll
            for (int mt = 0; mt < 4; ++mt)
                #pragma unroll
                for (int nt = 0; nt < 4; ++nt)
                    mma16816(acc[mt][nt], af[mt], &bf[nt >> 1][(nt & 1) * 2]);
        }

        if (st + 1 < NSTAGES) store_b(buf ^ 1);
        CP_WAIT0();
        __syncthreads();
    }

    // epilogue: fp32 accum -> round-to-fp16 values -> fp32 stores (match ref)
    const int crow = lid >> 2;
    const int ccol = (lid & 3) * 2;
    #pragma unroll
    for (int mt = 0; mt < 4; ++mt) {
        #pragma unroll
        for (int nt = 0; nt < 4; ++nt) {
            const int r = m0 + wm + mt * 16 + crow;
            const int c = n0 + wn + nt * 8 + ccol;
            float v0 = __half2float(__float2half_rn(acc[mt][nt][0]));
            float v1 = __half2float(__float2half_rn(acc[mt][nt][1]));
            float v2 = __half2float(__float2half_rn(acc[mt][nt][2]));
            float v3 = __half2float(__float2half_rn(acc[mt][nt][3]));
            *reinterpret_cast<float2*>(y + (size_t)r * N_TOTAL + c) =
                make_float2(v0, v1);
            *reinterpret_cast<float2*>(y + (size_t)(r + 8) * N_TOTAL + c) =
                make_float2(v2, v3);
        }
    }
}

extern "C" void kernel_launch(void* const* d_in, const int* in_sizes, int n_in,
                              void* d_out, int out_size) {
    const float* x      = (const float*)d_in[0];
    const int*   wp     = (const int*)d_in[1];
    const float* scales = (const float*)d_in[2];
    float*       y      = (float*)d_out;

    // 1) convert x + scales to fp16 scratch
    int nconv = XV + SV;
    cvt_kernel<<<(nconv + 255) / 256, 256>>>(x, scales);

    // 2) main GEMM
    cudaFuncSetAttribute(int4_gemm_hmma,
                         cudaFuncAttributeMaxDynamicSharedMemorySize,
                         SMEM_TOTAL);
    dim3 grid(M_TOTAL / MT, N_TOTAL / NT);   // (4, 86)
    int4_gemm_hmma<<<grid, THREADS, SMEM_TOTAL>>>(wp, y);
}

// round 5
// speedup vs baseline: 1.0342x; 1.0342x over previous
#include <cuda_runtime.h>
#include <cuda_fp16.h>
#include <cstdint>

// ---------------------------------------------------------------------------
// int4 group-quantized GEMM via mma.sync (HMMA), fp32 I/O (harness
// materializes fp16 jax arrays as fp32).
// y[512, 11008] = x[512, 4096] @ dequant(W)[11008, 4096]^T
// W: one byte per int32 (low nibble = even k, high nibble = odd k)
// w = scale[n, k/128] * (q - 8)
//
// R5: proper 3-stage cp.async pipeline for A (wait_group 1, prefetch dist 2),
// B double-buffered with register prefetch. Was: full drain (wait_group 0)
// every stage -> serialized prefetch -> tensor pipe 37%.
// ---------------------------------------------------------------------------

#define M_TOTAL 512
#define N_TOTAL 11008
#define K_TOTAL 4096
#define KW_INT  2048
#define NGROUPS 32

#define MT 128
#define NT 128
#define KT 64
#define NSTAGES (K_TOTAL / KT)  // 64
#define THREADS 256

#define SWZ128(bo) ((bo) ^ (((bo) >> 3) & 0x70))

#define STAGE_BYTES (128 * 128)                    // 16 KB
#define SMEM_A_OFF(buf) ((buf) * STAGE_BYTES)      // 3 buffers
#define SMEM_B_OFF(buf) (3 * STAGE_BYTES + (buf) * STAGE_BYTES)  // 2 buffers
#define SMEM_TOTAL (5 * STAGE_BYTES)               // 80 KB

// fp16 scratch (device globals: allocation-free scratch)
__device__ __align__(16) __half g_xh[M_TOTAL * K_TOTAL];   // 4 MB
__device__ __align__(16) __half g_sh[N_TOTAL * NGROUPS];   // 0.69 MB

// ---------------- PTX helpers ----------------
__device__ __forceinline__ uint32_t smem_u32(const void* p) {
    uint32_t a;
    asm("{ .reg .u64 t; cvta.to.shared.u64 t, %1; cvt.u32.u64 %0, t; }"
        : "=r"(a) : "l"(p));
    return a;
}

__device__ __forceinline__ void cp_async16(uint32_t saddr, const void* g) {
    asm volatile("cp.async.cg.shared.global [%0], [%1], 16;"
                 :: "r"(saddr), "l"(g) : "memory");
}
#define CP_COMMIT() asm volatile("cp.async.commit_group;" ::: "memory")
#define CP_WAIT1()  asm volatile("cp.async.wait_group 1;" ::: "memory")

__device__ __forceinline__ void ldsm4(uint32_t* r, uint32_t a) {
    asm volatile("ldmatrix.sync.aligned.m8n8.x4.shared.b16 {%0,%1,%2,%3}, [%4];"
                 : "=r"(r[0]), "=r"(r[1]), "=r"(r[2]), "=r"(r[3]) : "r"(a));
}

__device__ __forceinline__ void mma16816(float* c, const uint32_t* a,
                                         const uint32_t* b) {
    asm volatile(
        "mma.sync.aligned.m16n8k16.row.col.f32.f16.f16.f32 "
        "{%0,%1,%2,%3}, {%4,%5,%6,%7}, {%8,%9}, {%0,%1,%2,%3};"
        : "+f"(c[0]), "+f"(c[1]), "+f"(c[2]), "+f"(c[3])
        : "r"(a[0]), "r"(a[1]), "r"(a[2]), "r"(a[3]), "r"(b[0]), "r"(b[1]));
}

// dequant one packed byte -> half2 {lo-8, hi-8} * s2
// exact: (q | 0x6400) as fp16 == 1024 + q; subtract 1032.
__device__ __forceinline__ __half2 dq(int b, __half2 s2, __half2 c1032) {
    uint32_t u = (uint32_t)(b & 0xF) | (((uint32_t)b << 12) & 0x000F0000u)
               | 0x64006400u;
    __half2 h = __hsub2(*reinterpret_cast<__half2*>(&u), c1032);
    return __hmul2(h, s2);
}

// ---------------- fp32 -> fp16 conversion kernel ----------------
#define XV (M_TOTAL * K_TOTAL / 4)
#define SV (N_TOTAL * NGROUPS / 4)

__global__ void __launch_bounds__(256)
cvt_kernel(const float* __restrict__ x, const float* __restrict__ sc) {
    int i = blockIdx.x * blockDim.x + threadIdx.x;
    if (i < XV) {
        float4 f = reinterpret_cast<const float4*>(x)[i];
        union { __half2 h[2]; uint2 u; } p;
        p.h[0] = __floats2half2_rn(f.x, f.y);
        p.h[1] = __floats2half2_rn(f.z, f.w);
        reinterpret_cast<uint2*>(g_xh)[i] = p.u;
    } else if (i < XV + SV) {
        int j = i - XV;
        float4 f = reinterpret_cast<const float4*>(sc)[j];
        union { __half2 h[2]; uint2 u; } p;
        p.h[0] = __floats2half2_rn(f.x, f.y);
        p.h[1] = __floats2half2_rn(f.z, f.w);
        reinterpret_cast<uint2*>(g_sh)[j] = p.u;
    }
}

// ---------------- main GEMM kernel ----------------
__global__ void __launch_bounds__(THREADS, 2)
int4_gemm_hmma(const int* __restrict__ wp, float* __restrict__ y) {
    extern __shared__ __align__(1024) char smem[];
    const uint32_t sbase = smem_u32(smem);

    const int tid = threadIdx.x;
    const int wid = tid >> 5;
    const int lid = tid & 31;
    const int wm = (wid >> 2) * 64;
    const int wn = (wid & 3) * 32;

    const int m0 = blockIdx.x * MT;   // fast dim: 4 M tiles share weights in L2
    const int n0 = blockIdx.y * NT;

    const int jA = lid >> 3, rA = lid & 7;
    const int a_row_l = (jA & 1) * 8 + rA;
    const int a_kb_l  = (jA >> 1) * 16;
    const int b_row_l = (jA >> 1) * 8 + rA;
    const int b_kb_l  = (jA & 1) * 16;

    const int brow = tid >> 1;
    const int bseg = tid & 1;
    const __half2 c1032 = __half2half2(__ushort_as_half((unsigned short)0x6408));

    float acc[4][4][4];
    #pragma unroll
    for (int i = 0; i < 4; ++i)
        #pragma unroll
        for (int j = 0; j < 4; ++j)
            #pragma unroll
            for (int k = 0; k < 4; ++k) acc[i][j][k] = 0.f;

    auto issue_a = [&](int k0, int buf) {
        const uint32_t abase = sbase + SMEM_A_OFF(buf);
        #pragma unroll
        for (int it = 0; it < 4; ++it) {
            int t = tid + it * THREADS;
            int row = t >> 3, ch = t & 7;
            const void* src = g_xh + (size_t)(m0 + row) * K_TOTAL + k0 + ch * 8;
            uint32_t bo = row * 128 + ch * 16;
            cp_async16(abase + SWZ128(bo), src);
        }
    };

    int4 bp[4];
    __half2 s2;
    auto load_b = [&](int k0) {
        const int4* gb = reinterpret_cast<const int4*>(
            wp + (size_t)(n0 + brow) * KW_INT + (k0 >> 1) + bseg * 16);
        #pragma unroll
        for (int j = 0; j < 4; ++j) bp[j] = gb[j];
        const __half s = g_sh[(size_t)(n0 + brow) * NGROUPS + (k0 >> 7)];
        s2 = __half2half2(s);
    };

    auto store_b = [&](int buf) {
        #pragma unroll
        for (int j = 0; j < 4; ++j) {
            union { __half2 h[4]; uint4 u; } pk;
            pk.h[0] = dq(bp[j].x, s2, c1032);
            pk.h[1] = dq(bp[j].y, s2, c1032);
            pk.h[2] = dq(bp[j].z, s2, c1032);
            pk.h[3] = dq(bp[j].w, s2, c1032);
            uint32_t bo = brow * 128 + bseg * 64 + j * 16;
            *reinterpret_cast<uint4*>(smem + SMEM_B_OFF(buf) + SWZ128(bo)) = pk.u;
        }
    };

    // ---- prologue ----
    issue_a(0, 0);
    CP_COMMIT();                 // group: stage 0
    issue_a(KT, 1);
    CP_COMMIT();                 // group: stage 1
    load_b(0);
    store_b(0);                  // B buf 0
    CP_WAIT1();                  // stage-0 A landed (stage 1 may fly)
    __syncthreads();

    // ---- main loop ----
    int abuf_c = 0;              // compute A buffer (st % 3)
    int abuf_p = 2;              // prefetch A buffer ((st+2) % 3)
    #pragma unroll 1
    for (int st = 0; st < NSTAGES; ++st) {
        // prefetch A for stage st+2 (always commit to keep group count aligned)
        if (st + 2 < NSTAGES) issue_a((st + 2) * KT, abuf_p);
        CP_COMMIT();
        // prefetch B (regs) for stage st+1
        if (st + 1 < NSTAGES) load_b((st + 1) * KT);

        // compute stage st
        const uint32_t abase = sbase + SMEM_A_OFF(abuf_c);
        const uint32_t bbase = sbase + SMEM_B_OFF(st & 1);
        #pragma unroll
        for (int ks = 0; ks < 4; ++ks) {
            const int kb = ks * 32;
            uint32_t af[4][4];
            #pragma unroll
            for (int mt = 0; mt < 4; ++mt) {
                uint32_t bo = (uint32_t)(wm + mt * 16 + a_row_l) * 128
                            + kb + a_kb_l;
                ldsm4(af[mt], abase + SWZ128(bo));
            }
            uint32_t bf[2][4];
            #pragma unroll
            for (int np = 0; np < 2; ++np) {
                uint32_t bo = (uint32_t)(wn + np * 16 + b_row_l) * 128
                            + kb + b_kb_l;
                ldsm4(bf[np], bbase + SWZ128(bo));
            }
            #pragma unroll
            for (int mt = 0; mt < 4; ++mt)
                #pragma unroll
                for (int nt = 0; nt < 4; ++nt)
                    mma16816(acc[mt][nt], af[mt], &bf[nt >> 1][(nt & 1) * 2]);
        }

        // dequant + store B for stage st+1 (LDG latency hidden by compute)
        if (st + 1 < NSTAGES) store_b((st + 1) & 1);

        // stage st+1 A-copy must be done; stage st+2 may remain in flight
        CP_WAIT1();
        __syncthreads();

        abuf_c = (abuf_c == 2) ? 0 : abuf_c + 1;
        abuf_p = (abuf_p == 2) ? 0 : abuf_p + 1;
    }

    // ---- epilogue: fp32 accum -> fp16-rounded values -> fp32 stores ----
    const int crow = lid >> 2;
    const int ccol = (lid & 3) * 2;
    #pragma unroll
    for (int mt = 0; mt < 4; ++mt) {
        #pragma unroll
        for (int nt = 0; nt < 4; ++nt) {
            const int r = m0 + wm + mt * 16 + crow;
            const int c = n0 + wn + nt * 8 + ccol;
            float v0 = __half2float(__float2half_rn(acc[mt][nt][0]));
            float v1 = __half2float(__float2half_rn(acc[mt][nt][1]));
            float v2 = __half2float(__float2half_rn(acc[mt][nt][2]));
            float v3 = __half2float(__float2half_rn(acc[mt][nt][3]));
            *reinterpret_cast<float2*>(y + (size_t)r * N_TOTAL + c) =
                make_float2(v0, v1);
            *reinterpret_cast<float2*>(y + (size_t)(r + 8) * N_TOTAL + c) =
                make_float2(v2, v3);
        }
    }
}

extern "C" void kernel_launch(void* const* d_in, const int* in_sizes, int n_in,
                              void* d_out, int out_size) {
    const float* x      = (const float*)d_in[0];
    const int*   wp     = (const int*)d_in[1];
    const float* scales = (const float*)d_in[2];
    float*       y      = (float*)d_out;

    int nconv = XV + SV;
    cvt_kernel<<<(nconv + 255) / 256, 256>>>(x, scales);

    cudaFuncSetAttribute(int4_gemm_hmma,
                         cudaFuncAttributeMaxDynamicSharedMemorySize,
                         SMEM_TOTAL);
    dim3 grid(M_TOTAL / MT, N_TOTAL / NT);   // (4, 86)
    int4_gemm_hmma<<<grid, THREADS, SMEM_TOTAL>>>(wp, y);
}